// round 17
// baseline (speedup 1.0000x reference)
#include <cuda_runtime.h>

#define S 2048
#define C 4096
#define K 4
#define SCHUNK 8            // samples per block
#define BLKCH 1024          // channels per block (256 thr * 4 ch)

// Per-sample params, block-shared (tiny: 384 B).
struct Params {
    float4 w0[SCHUNK];      // tap0 weight per k
    float4 w1[SCHUNK];      // tap1 weight per k
    int4   r [SCHUNK];      // tap offset r = mi+4 in [0,7], per k
};

// Branchless tap select + accumulate: x[j] = w[r+j] via 3-level FSEL tree
// (r = 4*b2 + 2*b1 + b0), then 8 FFMA. No BSSY/BSYNC, no memory.
__device__ __forceinline__ void tap_sel(const float (&w)[12], int r, float W0, float W1,
                                        float& a0, float& a1, float& a2, float& a3) {
    const bool b2 = (r & 4) != 0;
    const bool b1 = (r & 2) != 0;
    const bool b0 = (r & 1) != 0;
    float z[8];
#pragma unroll
    for (int i = 0; i < 8; i++) z[i] = b2 ? w[i + 4] : w[i];
    float y[6];
#pragma unroll
    for (int i = 0; i < 6; i++) y[i] = b1 ? z[i + 2] : z[i];
    float x[5];
#pragma unroll
    for (int i = 0; i < 5; i++) x[i] = b0 ? y[i + 1] : y[i];
    a0 = fmaf(W0, x[0], fmaf(W1, x[1], a0));
    a1 = fmaf(W0, x[1], fmaf(W1, x[2], a1));
    a2 = fmaf(W0, x[2], fmaf(W1, x[3], a2));
    a3 = fmaf(W0, x[3], fmaf(W1, x[4], a3));
}

// Thread owns 4 consecutive channels; its 12-word window per component
// (comp[k][c-4 .. c+7], zero-padded at row edges) lives in REGISTERS.
// Per (sample,k): 19 FSEL + 8 FFMA, zero tap loads, zero branches.
__global__ void __launch_bounds__(256, 3)
smf_kernel(const float* __restrict__ comp,      // (K, C)
           const float* __restrict__ contrib,   // (S, K)
           const float* __restrict__ shift,     // (S, K)
           float* __restrict__ out)             // (S, C)
{
    __shared__ Params p;

    const int tid = threadIdx.x;
    const int B0  = blockIdx.x * BLKCH;
    const int s0  = blockIdx.y * SCHUNK;

    // ---- params: thread t<32 handles (sample t>>2, comp t&3) ----
    if (tid < SCHUNK * K) {
        const int sl = tid >> 2;
        const int kk = tid & 3;
        const float sh = __ldg(&shift[(s0 + sl) * K + kk]);
        const float wc = __ldg(&contrib[(s0 + sl) * K + kk]);
        const float m  = floorf(sh);
        const float f  = sh - m;
        int r = (int)m + 4;                      // shift in [-4,4) -> r in [0,7]
        r = max(0, min(7, r));
        const float w1 = wc * f;
        reinterpret_cast<float*>(&p.w0[sl])[kk] = wc - w1;
        reinterpret_cast<float*>(&p.w1[sl])[kk] = w1;
        reinterpret_cast<int*>(&p.r[sl])[kk]    = r;
    }

    // ---- register window: 3 aligned LDG.128 per component (L1-resident) ----
    const int c  = B0 + 4 * tid;                 // thread's first channel
    const int i4 = c >> 2;
    float w[K][12];
#pragma unroll
    for (int k = 0; k < K; k++) {
        const float4* c4 = reinterpret_cast<const float4*>(comp + k * C);
        const float4 z4 = make_float4(0.f, 0.f, 0.f, 0.f);
        const float4 va = (i4 > 0)         ? __ldg(&c4[i4 - 1]) : z4;
        const float4 vb = __ldg(&c4[i4]);
        const float4 vc = (i4 < C / 4 - 1) ? __ldg(&c4[i4 + 1]) : z4;
        w[k][0] = va.x; w[k][1]  = va.y; w[k][2]  = va.z; w[k][3]  = va.w;
        w[k][4] = vb.x; w[k][5]  = vb.y; w[k][6]  = vb.z; w[k][7]  = vb.w;
        w[k][8] = vc.x; w[k][9]  = vc.y; w[k][10] = vc.z; w[k][11] = vc.w;
    }
    __syncthreads();

    float* op = out + (size_t)s0 * C + c;

#pragma unroll 1
    for (int sl = 0; sl < SCHUNK; sl++) {
        const float4 W0 = p.w0[sl];              // broadcast LDS.128
        const float4 W1 = p.w1[sl];
        const int4   R  = p.r[sl];

        float a0 = 0.f, a1 = 0.f, a2 = 0.f, a3 = 0.f;
        tap_sel(w[0], R.x, W0.x, W1.x, a0, a1, a2, a3);
        tap_sel(w[1], R.y, W0.y, W1.y, a0, a1, a2, a3);
        tap_sel(w[2], R.z, W0.z, W1.z, a0, a1, a2, a3);
        tap_sel(w[3], R.w, W0.w, W1.w, a0, a1, a2, a3);

        *reinterpret_cast<float4*>(op) = make_float4(a0, a1, a2, a3);
        op += C;
    }
}

extern "C" void kernel_launch(void* const* d_in, const int* in_sizes, int n_in,
                              void* d_out, int out_size) {
    // metadata order: inputs (unused), components, contributions, shift
    const float* comp    = (const float*)d_in[1];
    const float* contrib = (const float*)d_in[2];
    const float* shift   = (const float*)d_in[3];
    float*       out     = (float*)d_out;

    dim3 grid(C / BLKCH, S / SCHUNK);   // (4, 256) = 1024 blocks
    smf_kernel<<<grid, 256>>>(comp, contrib, shift, out);
}